// round 2
// baseline (speedup 1.0000x reference)
#include <cuda_runtime.h>
#include <cuda_bf16.h>

#define M 512
#define NBLK 1024          // 512 row-blocks + 512 col-blocks
#define MARGIN 0.2f

// per-CTA partials: x = mean (0 if invalid), y = valid flag (0/1)
__device__ float2 g_partials[NBLK];

__global__ __launch_bounds__(512, 4)
void side_kernel(const float* __restrict__ scores,
                 const int* __restrict__ labels) {
    __shared__ __align__(16) float sadd[M];   // s_j + margin if neg else -1e30
    __shared__ int cnt_pos;
    __shared__ float warp_sums[16];

    const int b = blockIdx.x;
    const int t = threadIdx.x;
    const int lane = t & 31;

    // row blocks: b in [0,512) -> row b, contiguous access
    // col blocks: b in [512,1024) -> column (b-512), strided access (L2-resident)
    int idx;
    if (b < M) idx = b * M + t;
    else       idx = t * M + (b - M);

    const float s = scores[idx];
    const int lab = labels[idx];             // values are 0 or 1 (int32 on device)

    if (t == 0) cnt_pos = 0;
    __syncthreads();

    const bool pos = (lab == 1);
    sadd[t] = pos ? -1e30f : (s + MARGIN);

    unsigned bal = __ballot_sync(0xffffffffu, pos);
    if (lane == 0) atomicAdd(&cnt_pos, __popc(bal));
    __syncthreads();

    const int np = cnt_pos;
    const int nn = M - np;

    // acc = sum_j relu(sadd[j] - s_i); all threads compute, mask by pos at end.
    float a0 = 0.f, a1 = 0.f, a2 = 0.f, a3 = 0.f;
    const float4* sv = reinterpret_cast<const float4*>(sadd);
    #pragma unroll 8
    for (int j = 0; j < M / 4; j++) {
        float4 v = sv[j];                    // broadcast LDS.128 (all lanes same addr)
        a0 += fmaxf(v.x - s, 0.f);
        a1 += fmaxf(v.y - s, 0.f);
        a2 += fmaxf(v.z - s, 0.f);
        a3 += fmaxf(v.w - s, 0.f);
    }
    float acc = (a0 + a1) + (a2 + a3);
    acc = pos ? acc : 0.f;

    // deterministic reduction: warp shuffle tree, then cross-warp tree
    #pragma unroll
    for (int o = 16; o > 0; o >>= 1)
        acc += __shfl_down_sync(0xffffffffu, acc, o);
    if (lane == 0) warp_sums[t >> 5] = acc;
    __syncthreads();

    if (t < 32) {
        float v = (t < 16) ? warp_sums[t] : 0.f;
        #pragma unroll
        for (int o = 8; o > 0; o >>= 1)
            v += __shfl_down_sync(0xffffffffu, v, o);
        if (t == 0) {
            float cnt = (float)np * (float)nn;   // exact in fp32 (<= 2^18)
            bool valid = (np > 0) && (nn > 0);
            float2 p;
            p.x = valid ? (v / cnt) : 0.f;
            p.y = valid ? 1.f : 0.f;
            g_partials[b] = p;
        }
    }
}

__global__ void finalize_kernel(float* __restrict__ out) {
    __shared__ float sm[16], sv[16];
    const int t = threadIdx.x;
    const int lane = t & 31;

    float m = 0.f, v = 0.f;
    #pragma unroll
    for (int i = t; i < NBLK; i += 512) {
        float2 p = g_partials[i];
        m += p.x;
        v += p.y;
    }
    #pragma unroll
    for (int o = 16; o > 0; o >>= 1) {
        m += __shfl_down_sync(0xffffffffu, m, o);
        v += __shfl_down_sync(0xffffffffu, v, o);
    }
    if (lane == 0) { sm[t >> 5] = m; sv[t >> 5] = v; }
    __syncthreads();
    if (t < 32) {
        m = (t < 16) ? sm[t] : 0.f;
        v = (t < 16) ? sv[t] : 0.f;
        #pragma unroll
        for (int o = 8; o > 0; o >>= 1) {
            m += __shfl_down_sync(0xffffffffu, m, o);
            v += __shfl_down_sync(0xffffffffu, v, o);
        }
        if (t == 0) out[0] = m / v;
    }
}

extern "C" void kernel_launch(void* const* d_in, const int* in_sizes, int n_in,
                              void* d_out, int out_size) {
    const float* scores = (const float*)d_in[0];
    const int*   labels = (const int*)d_in[1];
    float* out = (float*)d_out;

    side_kernel<<<NBLK, 512>>>(scores, labels);
    finalize_kernel<<<1, 512>>>(out);
}

// round 3
// speedup vs baseline: 1.6747x; 1.6747x over previous
#include <cuda_runtime.h>
#include <cuda_bf16.h>

#define M 512
#define NBLK 1024          // 512 row-lines + 512 col-lines
#define MARGIN 0.2f

// per-CTA partials: x = mean (0 if invalid), y = valid flag (0/1)
__device__ float2 g_partials[NBLK];
__device__ int    g_count = 0;     // last-block ticket; reset by the finalizing block

__global__ __launch_bounds__(512, 4)
void side_kernel(const float* __restrict__ scores,
                 const int* __restrict__ labels,
                 float* __restrict__ out) {
    __shared__ __align__(16) float NV[M];   // compacted neg scores + margin
    __shared__ __align__(16) float PV[M];   // compacted pos scores
    __shared__ int   warp_pos_cnt[16];
    __shared__ float warp_sums[16];
    __shared__ bool  is_last;

    const int b    = blockIdx.x;
    const int t    = threadIdx.x;
    const int lane = t & 31;
    const int w    = t >> 5;

    // row lines: contiguous; col lines: strided (all L2-resident)
    int idx;
    if (b < M) idx = b * M + t;
    else       idx = t * M + (b - M);

    const float s   = scores[idx];
    const bool  pos = (labels[idx] == 1);

    // ---- compaction via ballot + warp-count scan ----
    const unsigned bal    = __ballot_sync(0xffffffffu, pos);
    const unsigned lt     = (1u << lane) - 1u;
    if (lane == 0) warp_pos_cnt[w] = __popc(bal);
    __syncthreads();

    int base_pos = 0, np = 0;
    #pragma unroll
    for (int k = 0; k < 16; k++) {
        int c = warp_pos_cnt[k];
        np += c;
        if (k < w) base_pos += c;
    }
    const int nn = M - np;

    if (pos) PV[base_pos + __popc(bal & lt)] = s;
    else     NV[(w * 32 - base_pos) + __popc(~bal & lt)] = s + MARGIN;
    __syncthreads();

    // ---- pair loop: thread (pid, half) scans half the neg list for pos pid ----
    const int pid  = t >> 1;
    const int half = t & 1;
    const int h    = (nn >> 1) & ~3;           // split point, multiple of 4
    const int j0   = half ? h  : 0;
    const int j1   = half ? nn : h;
    const int njv  = (j1 - j0) & ~3;           // vectorized count
    const float fcnt = (float)(j1 - j0);

    float total = 0.f;
    for (int i = pid; i < np; i += 256) {
        const float si = PV[i];
        float a0 = 0.f, a1 = 0.f, a2 = 0.f, a3 = 0.f;
        const float4* nv4 = reinterpret_cast<const float4*>(NV + j0);
        #pragma unroll 4
        for (int k = 0; k < (njv >> 2); k++) {
            float4 v = nv4[k];
            a0 += fmaxf(v.x, si);
            a1 += fmaxf(v.y, si);
            a2 += fmaxf(v.z, si);
            a3 += fmaxf(v.w, si);
        }
        float a = (a0 + a1) + (a2 + a3);
        for (int j = j0 + njv; j < j1; j++)     // tail (<=3, half==1 only)
            a += fmaxf(NV[j], si);
        total += a - fcnt * si;                 // relu sum via max identity
    }

    // ---- deterministic CTA reduction ----
    #pragma unroll
    for (int o = 16; o > 0; o >>= 1)
        total += __shfl_down_sync(0xffffffffu, total, o);
    if (lane == 0) warp_sums[w] = total;
    __syncthreads();

    if (t < 32) {
        float v = (t < 16) ? warp_sums[t] : 0.f;
        #pragma unroll
        for (int o = 8; o > 0; o >>= 1)
            v += __shfl_down_sync(0xffffffffu, v, o);
        if (t == 0) {
            const bool  valid = (np > 0) && (nn > 0);
            const float cnt   = (float)np * (float)nn;   // exact in fp32
            float2 p;
            p.x = valid ? (v / cnt) : 0.f;
            p.y = valid ? 1.f : 0.f;
            g_partials[b] = p;
            __threadfence();
            int c = atomicAdd(&g_count, 1);
            is_last = (c == NBLK - 1);
        }
    }
    __syncthreads();

    // ---- last block: fixed-order global reduction + finalize ----
    if (is_last) {
        float m = 0.f, vv = 0.f;
        #pragma unroll
        for (int i = t; i < NBLK; i += 512) {
            float2 p = g_partials[i];
            m  += p.x;
            vv += p.y;
        }
        #pragma unroll
        for (int o = 16; o > 0; o >>= 1) {
            m  += __shfl_down_sync(0xffffffffu, m, o);
            vv += __shfl_down_sync(0xffffffffu, vv, o);
        }
        __shared__ float sm[16], sv[16];
        if (lane == 0) { sm[w] = m; sv[w] = vv; }
        __syncthreads();
        if (t < 32) {
            m  = (t < 16) ? sm[t] : 0.f;
            vv = (t < 16) ? sv[t] : 0.f;
            #pragma unroll
            for (int o = 8; o > 0; o >>= 1) {
                m  += __shfl_down_sync(0xffffffffu, m, o);
                vv += __shfl_down_sync(0xffffffffu, vv, o);
            }
            if (t == 0) {
                out[0] = m / vv;
                g_count = 0;                    // reset for next graph replay
            }
        }
    }
}

extern "C" void kernel_launch(void* const* d_in, const int* in_sizes, int n_in,
                              void* d_out, int out_size) {
    const float* scores = (const float*)d_in[0];
    const int*   labels = (const int*)d_in[1];
    float* out = (float*)d_out;

    side_kernel<<<NBLK, 512>>>(scores, labels, out);
}